// round 1
// baseline (speedup 1.0000x reference)
#include <cuda_runtime.h>
#include <cuda_bf16.h>
#include <math.h>

#define S_LEN 2048
#define DMODEL 768
#define NHEAD 12
#define HDIM 64
#define FFN 3072
#define NLAYER 2

// ---------------- scratch (allocation-free: __device__ globals) ----------------
__device__ float g_x  [S_LEN * DMODEL];
__device__ float g_h  [S_LEN * DMODEL];
__device__ float g_qkv[S_LEN * 3 * DMODEL];
__device__ float g_att[S_LEN * DMODEL];
__device__ float g_ffn[S_LEN * FFN];

// ---------------- embed: x[t] = token_emb[idx[t]] + pe[t] ----------------
__global__ __launch_bounds__(256)
void embed_kernel(const int* __restrict__ idx, const float* __restrict__ emb,
                  const float* __restrict__ pe, float* __restrict__ x)
{
    int t = blockIdx.x;
    int tok = idx[t];
    const float* ep = emb + (size_t)tok * DMODEL;
    const float* pp = pe + (size_t)t * DMODEL;
    float* xp = x + (size_t)t * DMODEL;
    for (int d = threadIdx.x; d < DMODEL; d += 256)
        xp[d] = ep[d] + pp[d];
}

// ---------------- layernorm: one block per row ----------------
__device__ __forceinline__ float block_reduce_sum(float v, float* red)
{
    #pragma unroll
    for (int o = 16; o > 0; o >>= 1) v += __shfl_xor_sync(0xffffffffu, v, o);
    __syncthreads();                       // protect red[] reuse across calls
    if ((threadIdx.x & 31) == 0) red[threadIdx.x >> 5] = v;
    __syncthreads();
    float t = 0.f;
    #pragma unroll
    for (int i = 0; i < 8; i++) t += red[i];
    return t;
}

__global__ __launch_bounds__(256)
void ln_kernel(const float* __restrict__ x, const float* __restrict__ s,
               const float* __restrict__ b, float* __restrict__ o)
{
    __shared__ float red[8];
    int row = blockIdx.x;
    int tid = threadIdx.x;
    const float* xp = x + (size_t)row * DMODEL;
    float v0 = xp[tid], v1 = xp[tid + 256], v2 = xp[tid + 512];
    float mean = block_reduce_sum(v0 + v1 + v2, red) * (1.0f / DMODEL);
    float d0 = v0 - mean, d1 = v1 - mean, d2 = v2 - mean;
    float var = block_reduce_sum(d0 * d0 + d1 * d1 + d2 * d2, red) * (1.0f / DMODEL);
    float r = rsqrtf(var + 1e-5f);
    float* op = o + (size_t)row * DMODEL;
    op[tid]       = d0 * r * s[tid]       + b[tid];
    op[tid + 256] = d1 * r * s[tid + 256] + b[tid + 256];
    op[tid + 512] = d2 * r * s[tid + 512] + b[tid + 512];
}

// ---------------- SGEMM 128x128x8, 8x8 microtile, fused epilogue ----------------
// MODE 0: C = A@B + bias
// MODE 1: C = gelu(A@B + bias)          (exact erf gelu)
// MODE 2: C = A@B + bias + resid
template<int MODE>
__global__ __launch_bounds__(256)
void sgemm_kernel(const float* __restrict__ A, const float* __restrict__ B,
                  const float* __restrict__ bias, const float* __restrict__ resid,
                  float* __restrict__ C, int M, int N, int K)
{
    __shared__ float As[8][128];
    __shared__ float Bs[8][128];
    int tid = threadIdx.x;
    int m0 = blockIdx.y * 128;
    int n0 = blockIdx.x * 128;

    int ar = tid >> 1, ac = (tid & 1) << 2;          // A loader: row, k-col4
    int br = tid >> 5, bc = (tid & 31) << 2;         // B loader: k-row, n-col4

    const float* Ap = A + (size_t)(m0 + ar) * K + ac;
    const float* Bp = B + (size_t)br * N + n0 + bc;

    int tr = (tid >> 4) << 3;                        // 0..120 row offset
    int tc = (tid & 15) << 3;                        // 0..120 col offset

    float acc[8][8] = {};

    for (int k0 = 0; k0 < K; k0 += 8) {
        float4 a = *(const float4*)(Ap + k0);
        float4 bv = *(const float4*)(Bp + (size_t)k0 * N);
        As[ac + 0][ar] = a.x; As[ac + 1][ar] = a.y;
        As[ac + 2][ar] = a.z; As[ac + 3][ar] = a.w;
        *(float4*)&Bs[br][bc] = bv;
        __syncthreads();
        #pragma unroll
        for (int k = 0; k < 8; k++) {
            float ra[8], rb[8];
            *(float4*)(ra)     = *(const float4*)&As[k][tr];
            *(float4*)(ra + 4) = *(const float4*)&As[k][tr + 4];
            *(float4*)(rb)     = *(const float4*)&Bs[k][tc];
            *(float4*)(rb + 4) = *(const float4*)&Bs[k][tc + 4];
            #pragma unroll
            for (int i = 0; i < 8; i++)
                #pragma unroll
                for (int j = 0; j < 8; j++)
                    acc[i][j] = fmaf(ra[i], rb[j], acc[i][j]);
        }
        __syncthreads();
    }

    #pragma unroll
    for (int i = 0; i < 8; i++) {
        int row = m0 + tr + i;
        #pragma unroll
        for (int j = 0; j < 8; j++) {
            int col = n0 + tc + j;
            float c = acc[i][j] + bias[col];
            if (MODE == 1) c = 0.5f * c * (1.0f + erff(c * 0.70710678118654752f));
            if (MODE == 2) c += resid[(size_t)row * N + col];
            C[(size_t)row * N + col] = c;
        }
    }
}

// ---------------- causal flash attention: 1 thread = 1 query row ----------------
// qkv layout per token: [3][H][64] floats (q at h*64, k at 768+h*64, v at 1536+h*64)
__global__ __launch_bounds__(128)
void attn_kernel(const float* __restrict__ qkv, float* __restrict__ o)
{
    __shared__ float Ks[64][64];
    __shared__ float Vs[64][64];
    int h = blockIdx.y;
    int q0 = blockIdx.x * 128;
    int tid = threadIdx.x;
    int qi = q0 + tid;

    float q[HDIM];
    const float* qp = qkv + (size_t)qi * (3 * DMODEL) + h * HDIM;
    #pragma unroll
    for (int d = 0; d < HDIM; d += 4) {
        float4 v = *(const float4*)(qp + d);
        q[d] = v.x * 0.125f; q[d + 1] = v.y * 0.125f;
        q[d + 2] = v.z * 0.125f; q[d + 3] = v.w * 0.125f;
    }

    float acc[HDIM];
    #pragma unroll
    for (int d = 0; d < HDIM; d++) acc[d] = 0.f;
    float m = -1e30f, l = 0.f;

    for (int kt = 0; kt < q0 + 128; kt += 64) {
        __syncthreads();
        // cooperatively stage 64 K rows + 64 V rows
        for (int i = tid; i < 64 * 16; i += 128) {
            int r = i >> 4, c4 = (i & 15) << 2;
            const float* kp = qkv + (size_t)(kt + r) * (3 * DMODEL) + DMODEL + h * HDIM + c4;
            *(float4*)&Ks[r][c4] = *(const float4*)kp;
            *(float4*)&Vs[r][c4] = *(const float4*)(kp + DMODEL);
        }
        __syncthreads();
        int jmax = qi - kt + 1;
        if (jmax > 64) jmax = 64;
        for (int j = 0; j < jmax; j++) {
            float s = 0.f;
            #pragma unroll
            for (int d = 0; d < HDIM; d++) s = fmaf(q[d], Ks[j][d], s);
            float mn = fmaxf(m, s);
            float p = __expf(s - mn);
            float alpha = __expf(m - mn);
            l = l * alpha + p;
            #pragma unroll
            for (int d = 0; d < HDIM; d++)
                acc[d] = fmaf(acc[d], alpha, p * Vs[j][d]);
            m = mn;
        }
    }
    float inv = 1.0f / l;
    float* op = o + (size_t)qi * DMODEL + h * HDIM;
    #pragma unroll
    for (int d = 0; d < HDIM; d++) op[d] = acc[d] * inv;
}

// ---------------- host orchestration ----------------
extern "C" void kernel_launch(void* const* d_in, const int* in_sizes, int n_in,
                              void* d_out, int out_size)
{
    const int*   idx    = (const int*)  d_in[0];
    const float* temb   = (const float*)d_in[1];
    const float* pe     = (const float*)d_in[2];
    const float* qkv_w  = (const float*)d_in[3];
    const float* qkv_b  = (const float*)d_in[4];
    const float* out_w  = (const float*)d_in[5];
    const float* out_b  = (const float*)d_in[6];
    const float* ln1_s  = (const float*)d_in[7];
    const float* ln1_b  = (const float*)d_in[8];
    const float* ln2_s  = (const float*)d_in[9];
    const float* ln2_b  = (const float*)d_in[10];
    const float* w1     = (const float*)d_in[11];
    const float* b1     = (const float*)d_in[12];
    const float* w2     = (const float*)d_in[13];
    const float* b2     = (const float*)d_in[14];
    float* out = (float*)d_out;

    float *x, *hbuf, *qkvb, *att, *ffn;
    cudaGetSymbolAddress((void**)&x,    g_x);
    cudaGetSymbolAddress((void**)&hbuf, g_h);
    cudaGetSymbolAddress((void**)&qkvb, g_qkv);
    cudaGetSymbolAddress((void**)&att,  g_att);
    cudaGetSymbolAddress((void**)&ffn,  g_ffn);

    embed_kernel<<<S_LEN, 256>>>(idx, temb, pe, x);

    for (int l = 0; l < NLAYER; l++) {
        const float* lqkv_w = qkv_w + (size_t)l * DMODEL * 3 * DMODEL;
        const float* lqkv_b = qkv_b + (size_t)l * 3 * DMODEL;
        const float* lout_w = out_w + (size_t)l * DMODEL * DMODEL;
        const float* lout_b = out_b + (size_t)l * DMODEL;
        const float* lw1    = w1    + (size_t)l * DMODEL * FFN;
        const float* lb1    = b1    + (size_t)l * FFN;
        const float* lw2    = w2    + (size_t)l * FFN * DMODEL;
        const float* lb2    = b2    + (size_t)l * DMODEL;

        // h = LN1(x)
        ln_kernel<<<S_LEN, 256>>>(x, ln1_s + l * DMODEL, ln1_b + l * DMODEL, hbuf);
        // qkv = h @ qkv_w + qkv_b
        sgemm_kernel<0><<<dim3(3 * DMODEL / 128, S_LEN / 128), 256>>>(
            hbuf, lqkv_w, lqkv_b, nullptr, qkvb, S_LEN, 3 * DMODEL, DMODEL);
        // att = causal_attention(qkv)
        attn_kernel<<<dim3(S_LEN / 128, NHEAD), 128>>>(qkvb, att);
        // x = x + att @ out_w + out_b
        sgemm_kernel<2><<<dim3(DMODEL / 128, S_LEN / 128), 256>>>(
            att, lout_w, lout_b, x, x, S_LEN, DMODEL, DMODEL);
        // h = LN2(x)
        ln_kernel<<<S_LEN, 256>>>(x, ln2_s + l * DMODEL, ln2_b + l * DMODEL, hbuf);
        // ffn = gelu(h @ w1 + b1)
        sgemm_kernel<1><<<dim3(FFN / 128, S_LEN / 128), 256>>>(
            hbuf, lw1, lb1, nullptr, ffn, S_LEN, FFN, DMODEL);
        // x(out) = x + ffn @ w2 + b2   (last layer writes d_out directly)
        float* dst = (l == NLAYER - 1) ? out : x;
        sgemm_kernel<2><<<dim3(DMODEL / 128, S_LEN / 128), 256>>>(
            ffn, lw2, lb2, x, dst, S_LEN, DMODEL, FFN);
    }
}

// round 2
// speedup vs baseline: 1.0433x; 1.0433x over previous
#include <cuda_runtime.h>
#include <cuda_bf16.h>
#include <math.h>
#include <stdint.h>

#define S_LEN 2048
#define DMODEL 768
#define NHEAD 12
#define HDIM 64
#define FFN 3072
#define NLAYER 2
#define KSLAB 32
#define SSTR 136   // smem row stride (floats): bank = (8*k + col) % 32 -> conflict-free frags

// ---------------- scratch ----------------
__device__ float g_x  [S_LEN * DMODEL];
__device__ float g_h  [S_LEN * DMODEL];
__device__ float g_qkv[S_LEN * 3 * DMODEL];
__device__ float g_att[S_LEN * DMODEL];
__device__ float g_ffn[S_LEN * FFN];

// ---------------- helpers ----------------
__device__ __forceinline__ float to_tf32(float x) {
    uint32_t u;
    asm("cvt.rna.tf32.f32 %0, %1;" : "=r"(u) : "f"(x));
    return __uint_as_float(u);
}

__device__ __forceinline__ void mma_tf32(float* c, const uint32_t* a, const uint32_t* b) {
    asm volatile(
        "mma.sync.aligned.m16n8k8.row.col.f32.tf32.tf32.f32 "
        "{%0,%1,%2,%3}, {%4,%5,%6,%7}, {%8,%9}, {%0,%1,%2,%3};"
        : "+f"(c[0]), "+f"(c[1]), "+f"(c[2]), "+f"(c[3])
        : "r"(a[0]), "r"(a[1]), "r"(a[2]), "r"(a[3]), "r"(b[0]), "r"(b[1]));
}

// ---------------- embed ----------------
__global__ __launch_bounds__(256)
void embed_kernel(const int* __restrict__ idx, const float* __restrict__ emb,
                  const float* __restrict__ pe, float* __restrict__ x)
{
    int t = blockIdx.x;
    int tok = idx[t];
    const float* ep = emb + (size_t)tok * DMODEL;
    const float* pp = pe + (size_t)t * DMODEL;
    float* xp = x + (size_t)t * DMODEL;
    for (int d = threadIdx.x; d < DMODEL; d += 256)
        xp[d] = ep[d] + pp[d];
}

// ---------------- layernorm ----------------
__device__ __forceinline__ float block_reduce_sum(float v, float* red)
{
    #pragma unroll
    for (int o = 16; o > 0; o >>= 1) v += __shfl_xor_sync(0xffffffffu, v, o);
    __syncthreads();
    if ((threadIdx.x & 31) == 0) red[threadIdx.x >> 5] = v;
    __syncthreads();
    float t = 0.f;
    #pragma unroll
    for (int i = 0; i < 8; i++) t += red[i];
    return t;
}

__global__ __launch_bounds__(256)
void ln_kernel(const float* __restrict__ x, const float* __restrict__ s,
               const float* __restrict__ b, float* __restrict__ o)
{
    __shared__ float red[8];
    int row = blockIdx.x;
    int tid = threadIdx.x;
    const float* xp = x + (size_t)row * DMODEL;
    float v0 = xp[tid], v1 = xp[tid + 256], v2 = xp[tid + 512];
    float mean = block_reduce_sum(v0 + v1 + v2, red) * (1.0f / DMODEL);
    float d0 = v0 - mean, d1 = v1 - mean, d2 = v2 - mean;
    float var = block_reduce_sum(d0 * d0 + d1 * d1 + d2 * d2, red) * (1.0f / DMODEL);
    float r = rsqrtf(var + 1e-5f);
    float* op = o + (size_t)row * DMODEL;
    op[tid]       = d0 * r * s[tid]       + b[tid];
    op[tid + 256] = d1 * r * s[tid + 256] + b[tid + 256];
    op[tid + 512] = d2 * r * s[tid + 512] + b[tid + 512];
}

// ---------------- TF32 tensor-core GEMM, 128x128 tile, KSLAB=32 ----------------
// MODE 0: C = A@B + bias     MODE 1: gelu(A@B+bias)     MODE 2: A@B+bias+resid
// Warp layout: 2 (m) x 4 (n); warp tile 64x32; 4 mtiles x 4 ntiles of m16n8k8.
template<int MODE>
__global__ __launch_bounds__(256)
void tgemm_kernel(const float* __restrict__ A, const float* __restrict__ B,
                  const float* __restrict__ bias, const float* __restrict__ resid,
                  float* __restrict__ C, int M, int N, int K)
{
    __shared__ float As[KSLAB][SSTR];
    __shared__ float Bs[KSLAB][SSTR];

    int tid  = threadIdx.x;
    int lane = tid & 31, warp = tid >> 5;
    int warp_m = warp >> 2, warp_n = warp & 3;
    int m0 = blockIdx.y * 128, n0 = blockIdx.x * 128;

    // A loader: 32-consecutive-row groups (conflict-free smem transpose writes)
    int arow = tid & 127, aq = tid >> 7;     // quads aq, aq+2, aq+4, aq+6
    const float* Ag = A + (size_t)(m0 + arow) * K;

    float4 areg[4], breg[4];
    #pragma unroll
    for (int i = 0; i < 4; i++)
        areg[i] = *(const float4*)(Ag + (aq + 2 * i) * 4);
    #pragma unroll
    for (int i = 0; i < 4; i++) {
        int lin = tid + 256 * i;
        breg[i] = *(const float4*)(B + (size_t)(lin >> 5) * N + n0 + (lin & 31) * 4);
    }

    float c[4][4][4];
    #pragma unroll
    for (int mt = 0; mt < 4; mt++)
        #pragma unroll
        for (int nt = 0; nt < 4; nt++)
            #pragma unroll
            for (int i = 0; i < 4; i++) c[mt][nt][i] = 0.f;

    int mbase = warp_m * 64, nbase = warp_n * 32;
    int kk = lane & 3, ln4 = lane >> 2;

    for (int k0 = 0; k0 < K; k0 += KSLAB) {
        __syncthreads();
        #pragma unroll
        for (int i = 0; i < 4; i++) {
            int kq = (aq + 2 * i) * 4;
            As[kq + 0][arow] = to_tf32(areg[i].x);
            As[kq + 1][arow] = to_tf32(areg[i].y);
            As[kq + 2][arow] = to_tf32(areg[i].z);
            As[kq + 3][arow] = to_tf32(areg[i].w);
        }
        #pragma unroll
        for (int i = 0; i < 4; i++) {
            int lin = tid + 256 * i;
            float4 b = breg[i];
            b.x = to_tf32(b.x); b.y = to_tf32(b.y);
            b.z = to_tf32(b.z); b.w = to_tf32(b.w);
            *(float4*)&Bs[lin >> 5][(lin & 31) * 4] = b;
        }
        __syncthreads();

        int kn = k0 + KSLAB;
        if (kn < K) {
            #pragma unroll
            for (int i = 0; i < 4; i++)
                areg[i] = *(const float4*)(Ag + kn + (aq + 2 * i) * 4);
            #pragma unroll
            for (int i = 0; i < 4; i++) {
                int lin = tid + 256 * i;
                breg[i] = *(const float4*)(B + (size_t)(kn + (lin >> 5)) * N + n0 + (lin & 31) * 4);
            }
        }

        #pragma unroll
        for (int ks = 0; ks < KSLAB; ks += 8) {
            uint32_t bf[4][2];
            #pragma unroll
            for (int nt = 0; nt < 4; nt++) {
                bf[nt][0] = __float_as_uint(Bs[ks + kk][nbase + nt * 8 + ln4]);
                bf[nt][1] = __float_as_uint(Bs[ks + kk + 4][nbase + nt * 8 + ln4]);
            }
            #pragma unroll
            for (int mt = 0; mt < 4; mt++) {
                int rm = mbase + mt * 16;
                uint32_t af[4];
                af[0] = __float_as_uint(As[ks + kk][rm + ln4]);
                af[1] = __float_as_uint(As[ks + kk][rm + 8 + ln4]);
                af[2] = __float_as_uint(As[ks + kk + 4][rm + ln4]);
                af[3] = __float_as_uint(As[ks + kk + 4][rm + 8 + ln4]);
                #pragma unroll
                for (int nt = 0; nt < 4; nt++)
                    mma_tf32(c[mt][nt], af, bf[nt]);
            }
        }
    }

    // epilogue
    int row4 = lane >> 2, col2 = (lane & 3) * 2;
    #pragma unroll
    for (int mt = 0; mt < 4; mt++) {
        #pragma unroll
        for (int nt = 0; nt < 4; nt++) {
            int r0 = m0 + mbase + mt * 16 + row4;
            int cc = n0 + nbase + nt * 8 + col2;
            float2 bb = *(const float2*)(bias + cc);
            float v0 = c[mt][nt][0] + bb.x, v1 = c[mt][nt][1] + bb.y;
            float v2 = c[mt][nt][2] + bb.x, v3 = c[mt][nt][3] + bb.y;
            if (MODE == 1) {
                v0 = 0.5f * v0 * (1.0f + erff(v0 * 0.70710678118654752f));
                v1 = 0.5f * v1 * (1.0f + erff(v1 * 0.70710678118654752f));
                v2 = 0.5f * v2 * (1.0f + erff(v2 * 0.70710678118654752f));
                v3 = 0.5f * v3 * (1.0f + erff(v3 * 0.70710678118654752f));
            }
            if (MODE == 2) {
                float2 ra = *(const float2*)(resid + (size_t)r0 * N + cc);
                float2 rb = *(const float2*)(resid + (size_t)(r0 + 8) * N + cc);
                v0 += ra.x; v1 += ra.y; v2 += rb.x; v3 += rb.y;
            }
            float2 o0 = {v0, v1}, o1 = {v2, v3};
            *(float2*)(C + (size_t)r0 * N + cc) = o0;
            *(float2*)(C + (size_t)(r0 + 8) * N + cc) = o1;
        }
    }
}

// ---------------- causal flash attention: 4 threads per query ----------------
__global__ __launch_bounds__(256)
void attn_kernel(const float* __restrict__ qkv, float* __restrict__ o)
{
    __shared__ float Ks[64][64];
    __shared__ float Vs[64][64];
    int h = blockIdx.y;
    int qb = gridDim.x - 1 - blockIdx.x;          // heavy blocks first
    int q0 = qb * 64;
    int t = threadIdx.x;
    int qi = q0 + (t >> 2);
    int doff = (t & 3) * 16;

    float q[16];
    const float* qp = qkv + (size_t)qi * (3 * DMODEL) + h * HDIM + doff;
    #pragma unroll
    for (int d = 0; d < 16; d += 4) {
        float4 v = *(const float4*)(qp + d);
        q[d] = v.x * 0.125f; q[d + 1] = v.y * 0.125f;
        q[d + 2] = v.z * 0.125f; q[d + 3] = v.w * 0.125f;
    }

    float acc[16];
    #pragma unroll
    for (int d = 0; d < 16; d++) acc[d] = 0.f;
    float m = -1e30f, l = 0.f;

    for (int kt = 0; kt <= q0; kt += 64) {
        __syncthreads();
        #pragma unroll
        for (int i = 0; i < 4; i++) {
            int lin = t + 256 * i;
            int r = lin >> 4, c4 = (lin & 15) << 2;
            const float* kp = qkv + (size_t)(kt + r) * (3 * DMODEL) + DMODEL + h * HDIM + c4;
            *(float4*)&Ks[r][c4] = *(const float4*)kp;
            *(float4*)&Vs[r][c4] = *(const float4*)(kp + DMODEL);
        }
        __syncthreads();
        int jmax = qi - kt + 1;
        if (jmax > 64) jmax = 64;
        for (int j = 0; j < jmax; j++) {
            float s = 0.f;
            #pragma unroll
            for (int d = 0; d < 16; d += 4) {
                float4 kv = *(const float4*)&Ks[j][doff + d];
                s = fmaf(q[d], kv.x, s); s = fmaf(q[d + 1], kv.y, s);
                s = fmaf(q[d + 2], kv.z, s); s = fmaf(q[d + 3], kv.w, s);
            }
            s += __shfl_xor_sync(0xffffffffu, s, 1);
            s += __shfl_xor_sync(0xffffffffu, s, 2);
            if (s <= m) {                     // common path: 1 exp
                float p = __expf(s - m);
                l += p;
                #pragma unroll
                for (int d = 0; d < 16; d += 4) {
                    float4 vv = *(const float4*)&Vs[j][doff + d];
                    acc[d]     = fmaf(p, vv.x, acc[d]);
                    acc[d + 1] = fmaf(p, vv.y, acc[d + 1]);
                    acc[d + 2] = fmaf(p, vv.z, acc[d + 2]);
                    acc[d + 3] = fmaf(p, vv.w, acc[d + 3]);
                }
            } else {                          // rare: max update
                float al = __expf(m - s);
                l = l * al + 1.f;
                m = s;
                #pragma unroll
                for (int d = 0; d < 16; d += 4) {
                    float4 vv = *(const float4*)&Vs[j][doff + d];
                    acc[d]     = fmaf(acc[d], al, vv.x);
                    acc[d + 1] = fmaf(acc[d + 1], al, vv.y);
                    acc[d + 2] = fmaf(acc[d + 2], al, vv.z);
                    acc[d + 3] = fmaf(acc[d + 3], al, vv.w);
                }
            }
        }
    }
    float inv = 1.0f / l;
    float* op = o + (size_t)qi * DMODEL + h * HDIM + doff;
    #pragma unroll
    for (int d = 0; d < 16; d += 4) {
        float4 ov = {acc[d] * inv, acc[d + 1] * inv, acc[d + 2] * inv, acc[d + 3] * inv};
        *(float4*)(op + d) = ov;
    }
}

// ---------------- host orchestration ----------------
extern "C" void kernel_launch(void* const* d_in, const int* in_sizes, int n_in,
                              void* d_out, int out_size)
{
    const int*   idx    = (const int*)  d_in[0];
    const float* temb   = (const float*)d_in[1];
    const float* pe     = (const float*)d_in[2];
    const float* qkv_w  = (const float*)d_in[3];
    const float* qkv_b  = (const float*)d_in[4];
    const float* out_w  = (const float*)d_in[5];
    const float* out_b  = (const float*)d_in[6];
    const float* ln1_s  = (const float*)d_in[7];
    const float* ln1_b  = (const float*)d_in[8];
    const float* ln2_s  = (const float*)d_in[9];
    const float* ln2_b  = (const float*)d_in[10];
    const float* w1     = (const float*)d_in[11];
    const float* b1     = (const float*)d_in[12];
    const float* w2     = (const float*)d_in[13];
    const float* b2     = (const float*)d_in[14];
    float* out = (float*)d_out;

    float *x, *hbuf, *qkvb, *att, *ffn;
    cudaGetSymbolAddress((void**)&x,    g_x);
    cudaGetSymbolAddress((void**)&hbuf, g_h);
    cudaGetSymbolAddress((void**)&qkvb, g_qkv);
    cudaGetSymbolAddress((void**)&att,  g_att);
    cudaGetSymbolAddress((void**)&ffn,  g_ffn);

    embed_kernel<<<S_LEN, 256>>>(idx, temb, pe, x);

    for (int l = 0; l < NLAYER; l++) {
        const float* lqkv_w = qkv_w + (size_t)l * DMODEL * 3 * DMODEL;
        const float* lqkv_b = qkv_b + (size_t)l * 3 * DMODEL;
        const float* lout_w = out_w + (size_t)l * DMODEL * DMODEL;
        const float* lout_b = out_b + (size_t)l * DMODEL;
        const float* lw1    = w1    + (size_t)l * DMODEL * FFN;
        const float* lb1    = b1    + (size_t)l * FFN;
        const float* lw2    = w2    + (size_t)l * FFN * DMODEL;
        const float* lb2    = b2    + (size_t)l * DMODEL;

        ln_kernel<<<S_LEN, 256>>>(x, ln1_s + l * DMODEL, ln1_b + l * DMODEL, hbuf);
        tgemm_kernel<0><<<dim3(3 * DMODEL / 128, S_LEN / 128), 256>>>(
            hbuf, lqkv_w, lqkv_b, nullptr, qkvb, S_LEN, 3 * DMODEL, DMODEL);
        attn_kernel<<<dim3(S_LEN / 64, NHEAD), 256>>>(qkvb, att);
        tgemm_kernel<2><<<dim3(DMODEL / 128, S_LEN / 128), 256>>>(
            att, lout_w, lout_b, x, x, S_LEN, DMODEL, DMODEL);
        ln_kernel<<<S_LEN, 256>>>(x, ln2_s + l * DMODEL, ln2_b + l * DMODEL, hbuf);
        tgemm_kernel<1><<<dim3(FFN / 128, S_LEN / 128), 256>>>(
            hbuf, lw1, lb1, nullptr, ffn, S_LEN, FFN, DMODEL);
        float* dst = (l == NLAYER - 1) ? out : x;
        tgemm_kernel<2><<<dim3(DMODEL / 128, S_LEN / 128), 256>>>(
            ffn, lw2, lb2, x, dst, S_LEN, DMODEL, FFN);
    }
}

// round 4
// speedup vs baseline: 1.2409x; 1.1894x over previous
#include <cuda_runtime.h>
#include <cuda_fp16.h>
#include <math.h>
#include <stdint.h>

#define S_LEN 2048
#define DMODEL 768
#define NHEAD 12
#define HDIM 64
#define FFN 3072
#define NLAYER 2

// ---------------- scratch ----------------
__device__ float  g_x  [S_LEN * DMODEL];
__device__ __half g_h  [S_LEN * DMODEL];
__device__ float  g_qkv[S_LEN * 3 * DMODEL];
__device__ __half g_att[S_LEN * DMODEL];
__device__ __half g_ffn[S_LEN * FFN];
#define WT_LAYER 7077888
__device__ __half g_wt [NLAYER * WT_LAYER];

// ---------------- ptx helpers (baseline ISA only) ----------------
__device__ __forceinline__ uint32_t smem_u32(const void* p) {
    uint32_t a;
    asm("{ .reg .u64 t; cvta.to.shared.u64 t, %1; cvt.u32.u64 %0, t; }" : "=r"(a) : "l"(p));
    return a;
}
__device__ __forceinline__ void cp16(uint32_t s, const void* g) {
    asm volatile("cp.async.cg.shared.global [%0], [%1], 16;" :: "r"(s), "l"(g));
}
__device__ __forceinline__ void cp_commit() { asm volatile("cp.async.commit_group;" ::: "memory"); }
__device__ __forceinline__ void cp_wait1()  { asm volatile("cp.async.wait_group 1;" ::: "memory"); }
__device__ __forceinline__ void cp_wait0()  { asm volatile("cp.async.wait_group 0;" ::: "memory"); }

__device__ __forceinline__ void ldsm4(uint32_t* r, uint32_t addr) {
    asm volatile("ldmatrix.sync.aligned.m8n8.x4.shared.b16 {%0,%1,%2,%3}, [%4];"
        : "=r"(r[0]), "=r"(r[1]), "=r"(r[2]), "=r"(r[3]) : "r"(addr));
}
__device__ __forceinline__ void mma16816(float* c, const uint32_t* a, const uint32_t* b) {
    asm volatile(
        "mma.sync.aligned.m16n8k16.row.col.f32.f16.f16.f32 "
        "{%0,%1,%2,%3}, {%4,%5,%6,%7}, {%8,%9}, {%0,%1,%2,%3};"
        : "+f"(c[0]), "+f"(c[1]), "+f"(c[2]), "+f"(c[3])
        : "r"(a[0]), "r"(a[1]), "r"(a[2]), "r"(a[3]), "r"(b[0]), "r"(b[1]));
}

// ---------------- embed ----------------
__global__ __launch_bounds__(256)
void embed_kernel(const int* __restrict__ idx, const float* __restrict__ emb,
                  const float* __restrict__ pe, float* __restrict__ x)
{
    int t = blockIdx.x;
    int tok = idx[t];
    const float* ep = emb + (size_t)tok * DMODEL;
    const float* pp = pe + (size_t)t * DMODEL;
    float* xp = x + (size_t)t * DMODEL;
    for (int d = threadIdx.x; d < DMODEL; d += 256)
        xp[d] = ep[d] + pp[d];
}

// ---------------- weight transpose + fp16 convert: W[K,N] -> Wt[N,K] ----------------
__global__ __launch_bounds__(256)
void wconv_kernel(const float* __restrict__ W, __half* __restrict__ Wt, int K, int N)
{
    __shared__ float t[32][33];
    int n0 = blockIdx.x * 32, k0 = blockIdx.y * 32;
    int tx = threadIdx.x, ty = threadIdx.y;
    #pragma unroll
    for (int i = 0; i < 32; i += 8)
        t[ty + i][tx] = W[(size_t)(k0 + ty + i) * N + n0 + tx];
    __syncthreads();
    #pragma unroll
    for (int i = 0; i < 32; i += 8)
        Wt[(size_t)(n0 + ty + i) * K + k0 + tx] = __float2half(t[tx][ty + i]);
}

// ---------------- layernorm (fp32 in, fp16 out) ----------------
__device__ __forceinline__ float block_reduce_sum(float v, float* red)
{
    #pragma unroll
    for (int o = 16; o > 0; o >>= 1) v += __shfl_xor_sync(0xffffffffu, v, o);
    __syncthreads();
    if ((threadIdx.x & 31) == 0) red[threadIdx.x >> 5] = v;
    __syncthreads();
    float t = 0.f;
    #pragma unroll
    for (int i = 0; i < 8; i++) t += red[i];
    return t;
}

__global__ __launch_bounds__(256)
void ln_kernel(const float* __restrict__ x, const float* __restrict__ s,
               const float* __restrict__ b, __half* __restrict__ o)
{
    __shared__ float red[8];
    int row = blockIdx.x;
    int tid = threadIdx.x;
    const float* xp = x + (size_t)row * DMODEL;
    float v0 = xp[tid], v1 = xp[tid + 256], v2 = xp[tid + 512];
    float mean = block_reduce_sum(v0 + v1 + v2, red) * (1.0f / DMODEL);
    float d0 = v0 - mean, d1 = v1 - mean, d2 = v2 - mean;
    float var = block_reduce_sum(d0 * d0 + d1 * d1 + d2 * d2, red) * (1.0f / DMODEL);
    float r = rsqrtf(var + 1e-5f);
    __half* op = o + (size_t)row * DMODEL;
    op[tid]       = __float2half(d0 * r * s[tid]       + b[tid]);
    op[tid + 256] = __float2half(d1 * r * s[tid + 256] + b[tid + 256]);
    op[tid + 512] = __float2half(d2 * r * s[tid + 512] + b[tid + 512]);
}

// ---------------- fp16 HMMA GEMM: C[M,N] = A[M,K] @ Bt[N,K]^T ----------------
// 128x128 tile, k-slab 64 halves, double-buffered cp.async, ldmatrix fragments.
// MODE 0: +bias (float out)  MODE 1: gelu(+bias) (half out)  MODE 2: +bias+resid (float out)
#define SWC(c, r) (((c) ^ ((r) & 7)) << 4)
template<int MODE>
__global__ __launch_bounds__(256)
void hgemm_kernel(const __half* __restrict__ A, const __half* __restrict__ Bt,
                  const float* __restrict__ bias, const float* __restrict__ resid,
                  void* __restrict__ Cv, int M, int N, int K)
{
    extern __shared__ __align__(1024) char smem[];
    constexpr int STG = 32768;                 // per buffer: A 16KB + B 16KB

    uint32_t sb = smem_u32(smem);
    int tid = threadIdx.x, lane = tid & 31, warp = tid >> 5;
    int warp_m = warp >> 2, warp_n = warp & 3;
    int m0 = blockIdx.y * 128, n0 = blockIdx.x * 128;
    int mbase = warp_m * 64, nbase = warp_n * 32;

    const __half* Ag0 = A + (size_t)m0 * K;
    const __half* Bg0 = Bt + (size_t)n0 * K;
    int nslab = K >> 6;

    auto load_slab = [&](int s, int b) {
        uint32_t ab = sb + b * STG;
        uint32_t bb = ab + 16384;
        const __half* Ap = Ag0 + s * 64;
        const __half* Bp = Bg0 + s * 64;
        #pragma unroll
        for (int i = 0; i < 4; i++) {
            int idx = tid + 256 * i;
            int r = idx >> 3, c = idx & 7;
            cp16(ab + r * 128 + SWC(c, r), Ap + (size_t)r * K + c * 8);
        }
        #pragma unroll
        for (int i = 0; i < 4; i++) {
            int idx = tid + 256 * i;
            int r = idx >> 3, c = idx & 7;
            cp16(bb + r * 128 + SWC(c, r), Bp + (size_t)r * K + c * 8);
        }
        cp_commit();
    };

    float acc[4][4][4];
    #pragma unroll
    for (int mt = 0; mt < 4; mt++)
        #pragma unroll
        for (int nt = 0; nt < 4; nt++)
            #pragma unroll
            for (int i = 0; i < 4; i++) acc[mt][nt][i] = 0.f;

    load_slab(0, 0);

    int lrA = lane & 15, lcA = lane >> 4;                       // A: row, k-chunk
    int lrB = ((lane >> 4) << 3) + (lane & 7), lcB = (lane >> 3) & 1;  // B: n-row, k-chunk

    for (int s = 0; s < nslab; s++) {
        if (s + 1 < nslab) { load_slab(s + 1, (s + 1) & 1); cp_wait1(); }
        else               { cp_wait0(); }
        __syncthreads();

        uint32_t ab = sb + (s & 1) * STG;
        uint32_t bb = ab + 16384;

        #pragma unroll
        for (int k = 0; k < 4; k++) {
            uint32_t a[4][4], bq[2][4];
            #pragma unroll
            for (int mt = 0; mt < 4; mt++) {
                int r = mbase + mt * 16 + lrA;
                int c = k * 2 + lcA;
                ldsm4(a[mt], ab + r * 128 + SWC(c, r));
            }
            #pragma unroll
            for (int p = 0; p < 2; p++) {
                int r = nbase + p * 16 + lrB;
                int c = k * 2 + lcB;
                ldsm4(bq[p], bb + r * 128 + SWC(c, r));
            }
            #pragma unroll
            for (int mt = 0; mt < 4; mt++)
                #pragma unroll
                for (int nt = 0; nt < 4; nt++)
                    mma16816(acc[mt][nt], a[mt], bq[nt >> 1] + 2 * (nt & 1));
        }
        __syncthreads();
    }

    // epilogue (fragment: rows t/4, t/4+8; cols 2*(t%4)+{0,1})
    int row4 = lane >> 2, col2 = (lane & 3) * 2;
    #pragma unroll
    for (int mt = 0; mt < 4; mt++) {
        #pragma unroll
        for (int nt = 0; nt < 4; nt++) {
            int r0 = m0 + mbase + mt * 16 + row4;
            int cc = n0 + nbase + nt * 8 + col2;
            float2 bb = *(const float2*)(bias + cc);
            float v0 = acc[mt][nt][0] + bb.x, v1 = acc[mt][nt][1] + bb.y;
            float v2 = acc[mt][nt][2] + bb.x, v3 = acc[mt][nt][3] + bb.y;
            if (MODE == 1) {
                v0 = 0.5f * v0 * (1.0f + erff(v0 * 0.70710678118654752f));
                v1 = 0.5f * v1 * (1.0f + erff(v1 * 0.70710678118654752f));
                v2 = 0.5f * v2 * (1.0f + erff(v2 * 0.70710678118654752f));
                v3 = 0.5f * v3 * (1.0f + erff(v3 * 0.70710678118654752f));
            }
            if (MODE == 2) {
                float2 ra = *(const float2*)(resid + (size_t)r0 * N + cc);
                float2 rb = *(const float2*)(resid + (size_t)(r0 + 8) * N + cc);
                v0 += ra.x; v1 += ra.y; v2 += rb.x; v3 += rb.y;
            }
            if (MODE == 1) {
                __half* Cp = (__half*)Cv;
                *(__half2*)(Cp + (size_t)r0 * N + cc)       = __floats2half2_rn(v0, v1);
                *(__half2*)(Cp + (size_t)(r0 + 8) * N + cc) = __floats2half2_rn(v2, v3);
            } else {
                float* Cp = (float*)Cv;
                float2 o0 = {v0, v1}, o1 = {v2, v3};
                *(float2*)(Cp + (size_t)r0 * N + cc) = o0;
                *(float2*)(Cp + (size_t)(r0 + 8) * N + cc) = o1;
            }
        }
    }
}

// ---------------- causal flash attention: 4 threads/query, fp32 in, fp16 out ----------------
__global__ __launch_bounds__(256)
void attn_kernel(const float* __restrict__ qkv, __half* __restrict__ o)
{
    __shared__ float Ks[64][64];
    __shared__ float Vs[64][64];
    int h = blockIdx.y;
    int qb = gridDim.x - 1 - blockIdx.x;
    int q0 = qb * 64;
    int t = threadIdx.x;
    int qi = q0 + (t >> 2);
    int doff = (t & 3) * 16;

    float q[16];
    const float* qp = qkv + (size_t)qi * (3 * DMODEL) + h * HDIM + doff;
    #pragma unroll
    for (int d = 0; d < 16; d += 4) {
        float4 v = *(const float4*)(qp + d);
        q[d] = v.x * 0.125f; q[d + 1] = v.y * 0.125f;
        q[d + 2] = v.z * 0.125f; q[d + 3] = v.w * 0.125f;
    }

    float acc[16];
    #pragma unroll
    for (int d = 0; d < 16; d++) acc[d] = 0.f;
    float m = -1e30f, l = 0.f;

    for (int kt = 0; kt <= q0; kt += 64) {
        __syncthreads();
        #pragma unroll
        for (int i = 0; i < 4; i++) {
            int lin = t + 256 * i;
            int r = lin >> 4, c4 = (lin & 15) << 2;
            const float* kp = qkv + (size_t)(kt + r) * (3 * DMODEL) + DMODEL + h * HDIM + c4;
            *(float4*)&Ks[r][c4] = *(const float4*)kp;
            *(float4*)&Vs[r][c4] = *(const float4*)(kp + DMODEL);
        }
        __syncthreads();
        int jmax = qi - kt + 1;
        if (jmax > 64) jmax = 64;
        for (int j = 0; j < jmax; j++) {
            float s = 0.f;
            #pragma unroll
            for (int d = 0; d < 16; d += 4) {
                float4 kv = *(const float4*)&Ks[j][doff + d];
                s = fmaf(q[d], kv.x, s); s = fmaf(q[d + 1], kv.y, s);
                s = fmaf(q[d + 2], kv.z, s); s = fmaf(q[d + 3], kv.w, s);
            }
            s += __shfl_xor_sync(0xffffffffu, s, 1);
            s += __shfl_xor_sync(0xffffffffu, s, 2);
            if (s <= m) {
                float p = __expf(s - m);
                l += p;
                #pragma unroll
                for (int d = 0; d < 16; d += 4) {
                    float4 vv = *(const float4*)&Vs[j][doff + d];
                    acc[d]     = fmaf(p, vv.x, acc[d]);
                    acc[d + 1] = fmaf(p, vv.y, acc[d + 1]);
                    acc[d + 2] = fmaf(p, vv.z, acc[d + 2]);
                    acc[d + 3] = fmaf(p, vv.w, acc[d + 3]);
                }
            } else {
                float al = __expf(m - s);
                l = l * al + 1.f;
                m = s;
                #pragma unroll
                for (int d = 0; d < 16; d += 4) {
                    float4 vv = *(const float4*)&Vs[j][doff + d];
                    acc[d]     = fmaf(acc[d], al, vv.x);
                    acc[d + 1] = fmaf(acc[d + 1], al, vv.y);
                    acc[d + 2] = fmaf(acc[d + 2], al, vv.z);
                    acc[d + 3] = fmaf(acc[d + 3], al, vv.w);
                }
            }
        }
    }
    float inv = 1.0f / l;
    __half2* op = (__half2*)(o + (size_t)qi * DMODEL + h * HDIM + doff);
    #pragma unroll
    for (int d = 0; d < 8; d++)
        op[d] = __floats2half2_rn(acc[2 * d] * inv, acc[2 * d + 1] * inv);
}

// ---------------- host orchestration ----------------
extern "C" void kernel_launch(void* const* d_in, const int* in_sizes, int n_in,
                              void* d_out, int out_size)
{
    const int*   idx    = (const int*)  d_in[0];
    const float* temb   = (const float*)d_in[1];
    const float* pe     = (const float*)d_in[2];
    const float* qkv_w  = (const float*)d_in[3];
    const float* qkv_b  = (const float*)d_in[4];
    const float* out_w  = (const float*)d_in[5];
    const float* out_b  = (const float*)d_in[6];
    const float* ln1_s  = (const float*)d_in[7];
    const float* ln1_b  = (const float*)d_in[8];
    const float* ln2_s  = (const float*)d_in[9];
    const float* ln2_b  = (const float*)d_in[10];
    const float* w1     = (const float*)d_in[11];
    const float* b1     = (const float*)d_in[12];
    const float* w2     = (const float*)d_in[13];
    const float* b2     = (const float*)d_in[14];
    float* out = (float*)d_out;

    float *x, *qkvb;
    __half *hbuf, *att, *ffn, *wt;
    cudaGetSymbolAddress((void**)&x,    g_x);
    cudaGetSymbolAddress((void**)&hbuf, g_h);
    cudaGetSymbolAddress((void**)&qkvb, g_qkv);
    cudaGetSymbolAddress((void**)&att,  g_att);
    cudaGetSymbolAddress((void**)&ffn,  g_ffn);
    cudaGetSymbolAddress((void**)&wt,   g_wt);

    constexpr int SMB = 65536;
    cudaFuncSetAttribute(hgemm_kernel<0>, cudaFuncAttributeMaxDynamicSharedMemorySize, SMB);
    cudaFuncSetAttribute(hgemm_kernel<1>, cudaFuncAttributeMaxDynamicSharedMemorySize, SMB);
    cudaFuncSetAttribute(hgemm_kernel<2>, cudaFuncAttributeMaxDynamicSharedMemorySize, SMB);

    // weight prepass: transpose + fp16 convert
    const size_t OQKV = 0, OOUT = 1769472, OW1 = 2359296, OW2 = 4718592;
    for (int l = 0; l < NLAYER; l++) {
        __half* wl = wt + (size_t)l * WT_LAYER;
        wconv_kernel<<<dim3(3 * DMODEL / 32, DMODEL / 32), dim3(32, 8)>>>(
            qkv_w + (size_t)l * DMODEL * 3 * DMODEL, wl + OQKV, DMODEL, 3 * DMODEL);
        wconv_kernel<<<dim3(DMODEL / 32, DMODEL / 32), dim3(32, 8)>>>(
            out_w + (size_t)l * DMODEL * DMODEL, wl + OOUT, DMODEL, DMODEL);
        wconv_kernel<<<dim3(FFN / 32, DMODEL / 32), dim3(32, 8)>>>(
            w1 + (size_t)l * DMODEL * FFN, wl + OW1, DMODEL, FFN);
        wconv_kernel<<<dim3(DMODEL / 32, FFN / 32), dim3(32, 8)>>>(
            w2 + (size_t)l * FFN * DMODEL, wl + OW2, FFN, DMODEL);
    }

    embed_kernel<<<S_LEN, 256>>>(idx, temb, pe, x);

    for (int l = 0; l < NLAYER; l++) {
        __half* wl = wt + (size_t)l * WT_LAYER;
        const float* lqkv_b = qkv_b + (size_t)l * 3 * DMODEL;
        const float* lout_b = out_b + (size_t)l * DMODEL;
        const float* lb1    = b1 + (size_t)l * FFN;
        const float* lb2    = b2 + (size_t)l * DMODEL;

        ln_kernel<<<S_LEN, 256>>>(x, ln1_s + l * DMODEL, ln1_b + l * DMODEL, hbuf);
        hgemm_kernel<0><<<dim3(3 * DMODEL / 128, S_LEN / 128), 256, SMB>>>(
            hbuf, wl + OQKV, lqkv_b, nullptr, qkvb, S_LEN, 3 * DMODEL, DMODEL);
        attn_kernel<<<dim3(S_LEN / 64, NHEAD), 256>>>(qkvb, att);
        hgemm_kernel<2><<<dim3(DMODEL / 128, S_LEN / 128), 256, SMB>>>(
            att, wl + OOUT, lout_b, x, x, S_LEN, DMODEL, DMODEL);
        ln_kernel<<<S_LEN, 256>>>(x, ln2_s + l * DMODEL, ln2_b + l * DMODEL, hbuf);
        hgemm_kernel<1><<<dim3(FFN / 128, S_LEN / 128), 256, SMB>>>(
            hbuf, wl + OW1, lb1, nullptr, ffn, S_LEN, FFN, DMODEL);
        float* dst = (l == NLAYER - 1) ? out : x;
        hgemm_kernel<2><<<dim3(DMODEL / 128, S_LEN / 128), 256, SMB>>>(
            ffn, wl + OW2, lb2, x, dst, S_LEN, DMODEL, FFN);
    }
}